// round 14
// baseline (speedup 1.0000x reference)
#include <cuda_runtime.h>
#include <cuda_bf16.h>
#include <cuda_fp16.h>
#include <cstdint>

// LocalWindowAttention3D R14: 256 thr/CTA, 2 CTAs/SM (smem 112KB), outer x2
// task loops. bf16 3-term QKV/QK, fp16 PV (P,V,O single) + 2-term Wout.

namespace {
constexpr int CDIM = 128;
constexpr int SDIM = 110592;      // 48^3
constexpr int NWIN = 1728;        // 12^3
constexpr int XP   = 72;          // xs gather pitch (floats)
// ---- smem plan (bytes), total 114688 ----
constexpr int O_XB  = 0;          // x frags uint4[2048] = 32768 (dead after QKV)
constexpr int O_OF  = 0;          // out frags uint2[2048] = 16384 (aliases xb)
constexpr int O_QFH = 32768;      // 2048 u32 = 8192 each... (uint2[2048] = 16384)
constexpr int O_QFL = 49152;
constexpr int O_KFH = 65536;
constexpr int O_KFL = 81920;      // -> 98304
constexpr int O_VF  = 98304;      // u32[16*256] = 16384 -> 114688
constexpr int O_XS  = 32768;      // gather scratch 36864 (overlaps qf/kf, dead before QKV)
constexpr int SMEM_BYTES = 114688;
constexpr int VST = 256;          // vf cblk stride in u32 cells (conflict-free)
}

// Weight fragment images: [ch(8)][wrb(4)][ks(8)][lane(32)] uint4.
// ch 0..5 = Wqkv bf16x2 pairs (c0+t4, c0+t4+4), (c0+8+t4, c0+12+t4).
// ch 6..7 = Wout fp16x2 pairs (c0+2t4, +1), (c0+2t4+8, +9).
__device__ uint4 gWh[8 * 4 * 8 * 32];
__device__ uint4 gWl[8 * 4 * 8 * 32];

__device__ __forceinline__ void split2(float a, float b, uint32_t& hi, uint32_t& lo) {
    __nv_bfloat162 h = __floats2bfloat162_rn(a, b);
    const float ra = a - __low2float(h);
    const float rb = b - __high2float(h);
    __nv_bfloat162 l = __floats2bfloat162_rn(ra, rb);
    hi = *reinterpret_cast<uint32_t*>(&h);
    lo = *reinterpret_cast<uint32_t*>(&l);
}
__device__ __forceinline__ void split2h(float a, float b, uint32_t& hi, uint32_t& lo) {
    __half2 h = __floats2half2_rn(a, b);
    const float ra = a - __half2float(__low2half(h));
    const float rb = b - __half2float(__high2half(h));
    __half2 l = __floats2half2_rn(ra, rb);
    hi = *reinterpret_cast<uint32_t*>(&h);
    lo = *reinterpret_cast<uint32_t*>(&l);
}
__device__ __forceinline__ uint32_t packh(float a, float b) {
    __half2 h = __floats2half2_rn(a, b);
    return *reinterpret_cast<uint32_t*>(&h);
}
__device__ __forceinline__ float ex2(float x) {
    float r;
    asm("ex2.approx.f32 %0, %1;" : "=f"(r) : "f"(x));
    return r;
}
__device__ __forceinline__ void mma_bf16(float* d, uint32_t a0, uint32_t a1, uint32_t a2,
                                         uint32_t a3, uint32_t b0, uint32_t b1) {
    asm volatile(
        "mma.sync.aligned.m16n8k16.row.col.f32.bf16.bf16.f32 "
        "{%0,%1,%2,%3}, {%4,%5,%6,%7}, {%8,%9}, {%0,%1,%2,%3};"
        : "+f"(d[0]), "+f"(d[1]), "+f"(d[2]), "+f"(d[3])
        : "r"(a0), "r"(a1), "r"(a2), "r"(a3), "r"(b0), "r"(b1));
}
__device__ __forceinline__ void mma_f16(float* d, uint32_t a0, uint32_t a1, uint32_t a2,
                                        uint32_t a3, uint32_t b0, uint32_t b1) {
    asm volatile(
        "mma.sync.aligned.m16n8k16.row.col.f32.f16.f16.f32 "
        "{%0,%1,%2,%3}, {%4,%5,%6,%7}, {%8,%9}, {%0,%1,%2,%3};"
        : "+f"(d[0]), "+f"(d[1]), "+f"(d[2]), "+f"(d[3])
        : "r"(a0), "r"(a1), "r"(a2), "r"(a3), "r"(b0), "r"(b1));
}

__global__ void prep_weights(const float* __restrict__ Wqkv, const float* __restrict__ Wout) {
    const int idx = blockIdx.x * 256 + threadIdx.x;     // 8192 frags
    if (idx >= 8192) return;
    const int lane = idx & 31;
    const int ks   = (idx >> 5) & 7;
    const int wrb  = (idx >> 8) & 3;
    const int ch   = idx >> 10;
    const int g = lane >> 2, t4 = lane & 3;
    const int e0 = ch * 64 + wrb * 16 + g;
    const float* W0 = (ch < 6) ? (Wqkv + (size_t)e0 * CDIM) : (Wout + (size_t)(e0 - 384) * CDIM);
    const float* W8 = W0 + 8 * CDIM;
    const int c0 = ks * 16;
    uint4 h, l;
    if (ch < 6) {
        const int cs0 = c0 + t4, cs1 = c0 + t4 + 4, cs2 = c0 + 8 + t4, cs3 = c0 + 12 + t4;
        split2(W0[cs0], W0[cs1], h.x, l.x);
        split2(W8[cs0], W8[cs1], h.y, l.y);
        split2(W0[cs2], W0[cs3], h.z, l.z);
        split2(W8[cs2], W8[cs3], h.w, l.w);
    } else {
        const int cs0 = c0 + t4 * 2, cs1 = cs0 + 1, cs2 = cs0 + 8, cs3 = cs0 + 9;
        split2h(W0[cs0], W0[cs1], h.x, l.x);
        split2h(W8[cs0], W8[cs1], h.y, l.y);
        split2h(W0[cs2], W0[cs3], h.z, l.z);
        split2h(W8[cs2], W8[cs3], h.w, l.w);
    }
    gWh[idx] = h;
    gWl[idx] = l;
}

__global__ __launch_bounds__(256, 2)
void lwa3d_mma(const float* __restrict__ x, const float* __restrict__ bout,
               float* __restrict__ out)
{
    extern __shared__ char smc[];
    uint2* qfh = reinterpret_cast<uint2*>(smc + O_QFH);
    uint2* qfl = reinterpret_cast<uint2*>(smc + O_QFL);
    uint2* kfh = reinterpret_cast<uint2*>(smc + O_KFH);
    uint2* kfl = reinterpret_cast<uint2*>(smc + O_KFL);
    uint32_t* qfhw = reinterpret_cast<uint32_t*>(smc + O_QFH);
    uint32_t* qflw = reinterpret_cast<uint32_t*>(smc + O_QFL);
    uint32_t* kfhw = reinterpret_cast<uint32_t*>(smc + O_KFH);
    uint32_t* kflw = reinterpret_cast<uint32_t*>(smc + O_KFL);
    uint32_t* vf = reinterpret_cast<uint32_t*>(smc + O_VF);
    uint2* ofp = reinterpret_cast<uint2*>(smc + O_OF);
    float* xs  = reinterpret_cast<float*>(smc + O_XS);
    uint4* xbp = reinterpret_cast<uint4*>(smc + O_XB);

    const int tid  = threadIdx.x;
    const int wid  = tid >> 5;
    const int lane = tid & 31;
    const int g    = lane >> 2;
    const int t4   = lane & 3;
    const int n = blockIdx.x;
    const int b = blockIdx.y;
    // 128^-0.5 * log2(e): Q pre-scale so softmax uses ex2 directly
    const float scale = 0.12751741578f;

    // ---------- gather x window into xs [128c][64t] ----------
    {
        const int ndi = n / 144, nhi = (n / 12) % 12, nwi = n % 12;
        const float* xb = x + (size_t)b * CDIM * SDIM;
        const int sbase = ((ndi * 4) * 48 + nhi * 4) * 48 + nwi * 4;
        for (int i = tid; i < CDIM * 16; i += 256) {
            const int c = i >> 4;
            const int gg = i & 15;
            const int s0 = sbase + ((gg >> 2) * 48 + (gg & 3)) * 48;
            *reinterpret_cast<float4*>(xs + c * XP + gg * 4) =
                *reinterpret_cast<const float4*>(xb + (size_t)c * SDIM + s0);
        }
    }
    __syncthreads();

    // ---------- build packed bf16 hi/lo x B-fragments ----------
    for (int cell = tid; cell < 2048; cell += 256) {
        const int l2 = cell & 31;
        const int ks = (cell >> 5) & 7;
        const int tb = cell >> 8;
        const int t  = tb * 8 + (l2 >> 2);
        const int c0 = ks * 16 + (l2 & 3);
        uint32_t h0, l0, h1, l1;
        split2(xs[c0 * XP + t], xs[(c0 + 4) * XP + t], h0, l0);
        split2(xs[(c0 + 8) * XP + t], xs[(c0 + 12) * XP + t], h1, l1);
        xbp[cell] = make_uint4(h0, h1, l0, l1);
    }
    __syncthreads();

    // ---------- QKV = Wqkv @ x : 16 groups of 3 chunks; 8 warps x 2 iters ----------
    #pragma unroll 1
    for (int ti = 0; ti < 2; ++ti) {
        const int gw = wid + ti * 8;
        const int nhalf = gw & 1;
        const int p0 = (gw >> 1) * 3;           // 3 (ch,wrb) pairs
        const uint4* ph[3];
        const uint4* pl[3];
        #pragma unroll
        for (int i = 0; i < 3; ++i) {
            const int p = p0 + i;
            ph[i] = gWh + (p * 8) * 32 + lane;   // p == ch*4+wrb
            pl[i] = gWl + (p * 8) * 32 + lane;
        }
        float d[3][4][4];
        #pragma unroll
        for (int i = 0; i < 3; ++i)
            #pragma unroll
            for (int nt = 0; nt < 4; ++nt)
                #pragma unroll
                for (int j = 0; j < 4; ++j) d[i][nt][j] = 0.f;

        #pragma unroll 2
        for (int ks = 0; ks < 8; ++ks) {
            uint4 bb[4];
            #pragma unroll
            for (int nt = 0; nt < 4; ++nt)
                bb[nt] = xbp[((nhalf * 4 + nt) * 8 + ks) * 32 + lane];
            #pragma unroll
            for (int i = 0; i < 3; ++i) {
                const uint4 ah = __ldg(ph[i] + ks * 32);
                const uint4 al = __ldg(pl[i] + ks * 32);
                #pragma unroll
                for (int nt = 0; nt < 4; ++nt) {
                    mma_bf16(d[i][nt], ah.x, ah.y, ah.z, ah.w, bb[nt].x, bb[nt].y);
                    mma_bf16(d[i][nt], ah.x, ah.y, ah.z, ah.w, bb[nt].z, bb[nt].w);
                    mma_bf16(d[i][nt], al.x, al.y, al.z, al.w, bb[nt].x, bb[nt].y);
                }
            }
        }

        // epilogues
        #pragma unroll
        for (int i = 0; i < 3; ++i) {
            const int p = p0 + i;
            const int ch  = p >> 2;
            const int wrb = p & 3;
            if (ch < 4) {
                const int h = (ch & 1) * 4 + wrb;
                uint32_t* fh = (ch < 2) ? qfhw : kfhw;
                uint32_t* fl = (ch < 2) ? qflw : kflw;
                const float sc = (ch < 2) ? scale : 1.f;
                #pragma unroll
                for (int nt = 0; nt < 4; ++nt) {
                    const int tb = nhalf * 4 + nt;
                    uint32_t hh0, ll0, hh1, ll1;
                    split2(d[i][nt][0] * sc, d[i][nt][2] * sc, hh0, ll0);
                    split2(d[i][nt][1] * sc, d[i][nt][3] * sc, hh1, ll1);
                    const int base = (tb * 8 + h) * 32 + (g & 3);
                    const int i0 = ((base + (2 * t4) * 4) << 1) | (g >> 2);
                    const int i1 = ((base + (2 * t4 + 1) * 4) << 1) | (g >> 2);
                    fh[i0] = hh0; fl[i0] = ll0;
                    fh[i1] = hh1; fl[i1] = ll1;
                }
            } else {
                // V: single fp16
                const int cb0 = (ch & 1) * 8 + wrb * 2;
                const int lane2 = g * 4 + t4;
                #pragma unroll
                for (int nt = 0; nt < 4; ++nt) {
                    const int kb = nhalf * 4 + nt;
                    vf[cb0 * VST + kb * 32 + lane2]       = packh(d[i][nt][0], d[i][nt][1]);
                    vf[(cb0 + 1) * VST + kb * 32 + lane2] = packh(d[i][nt][2], d[i][nt][3]);
                }
            }
        }
    }
    __syncthreads();

    // ---------- attention: 16 tasks (head, q-pair); 8 warps x 2 iters ----------
    #pragma unroll 1
    for (int ti = 0; ti < 2; ++ti) {
        const int gw  = wid + ti * 8;
        const int h   = gw >> 1;
        const int mb0 = (gw & 1) * 2;

        const int cA0 = (2 * mb0 * 8 + h) * 32 + lane;
        const int cA1 = (2 * (mb0 + 1) * 8 + h) * 32 + lane;
        const uint2 A0h0 = qfh[cA0], A0h1 = qfh[cA0 + 256];
        const uint2 A0l0 = qfl[cA0], A0l1 = qfl[cA0 + 256];
        const uint2 A1h0 = qfh[cA1], A1h1 = qfh[cA1 + 256];
        const uint2 A1l0 = qfl[cA1], A1l1 = qfl[cA1 + 256];

        uint32_t ep0[8][2], ep1[8][2];
        float s00 = 0.f, s01 = 0.f, s10 = 0.f, s11 = 0.f;
        #pragma unroll 2
        for (int kb = 0; kb < 8; ++kb) {
            const int cB = (kb * 8 + h) * 32 + lane;
            const uint2 Bh = kfh[cB];
            const uint2 Bl = kfl[cB];
            float d0[4] = {0.f, 0.f, 0.f, 0.f};
            float d1[4] = {0.f, 0.f, 0.f, 0.f};
            mma_bf16(d0, A0h0.x, A0h1.x, A0h0.y, A0h1.y, Bh.x, Bh.y);
            mma_bf16(d0, A0h0.x, A0h1.x, A0h0.y, A0h1.y, Bl.x, Bl.y);
            mma_bf16(d0, A0l0.x, A0l1.x, A0l0.y, A0l1.y, Bh.x, Bh.y);
            mma_bf16(d1, A1h0.x, A1h1.x, A1h0.y, A1h1.y, Bh.x, Bh.y);
            mma_bf16(d1, A1h0.x, A1h1.x, A1h0.y, A1h1.y, Bl.x, Bl.y);
            mma_bf16(d1, A1l0.x, A1l1.x, A1l0.y, A1l1.y, Bh.x, Bh.y);
            const float e00 = ex2(d0[0]);
            const float e01 = ex2(d0[1]);
            const float e02 = ex2(d0[2]);
            const float e03 = ex2(d0[3]);
            s00 += e00 + e01;
            s01 += e02 + e03;
            ep0[kb][0] = packh(e00, e01);
            ep0[kb][1] = packh(e02, e03);
            const float e10 = ex2(d1[0]);
            const float e11 = ex2(d1[1]);
            const float e12 = ex2(d1[2]);
            const float e13 = ex2(d1[3]);
            s10 += e10 + e11;
            s11 += e12 + e13;
            ep1[kb][0] = packh(e10, e11);
            ep1[kb][1] = packh(e12, e13);
        }
        s00 += __shfl_xor_sync(0xFFFFFFFF, s00, 1);
        s00 += __shfl_xor_sync(0xFFFFFFFF, s00, 2);
        s01 += __shfl_xor_sync(0xFFFFFFFF, s01, 1);
        s01 += __shfl_xor_sync(0xFFFFFFFF, s01, 2);
        s10 += __shfl_xor_sync(0xFFFFFFFF, s10, 1);
        s10 += __shfl_xor_sync(0xFFFFFFFF, s10, 2);
        s11 += __shfl_xor_sync(0xFFFFFFFF, s11, 1);
        s11 += __shfl_xor_sync(0xFFFFFFFF, s11, 2);

        // ---- PV (fp16, V single): V frags loaded once, used by both q-blocks ----
        float oA0[4] = {0.f, 0.f, 0.f, 0.f};
        float oB0[4] = {0.f, 0.f, 0.f, 0.f};
        float oA1[4] = {0.f, 0.f, 0.f, 0.f};
        float oB1[4] = {0.f, 0.f, 0.f, 0.f};
        #pragma unroll
        for (int ks = 0; ks < 4; ++ks) {
            const int ib = (2 * h) * VST + (2 * ks) * 32 + lane;
            const uint32_t v0 = vf[ib],       v1 = vf[ib + 32];
            const uint32_t w0 = vf[ib + VST], w1 = vf[ib + VST + 32];
            const uint32_t a00 = ep0[2 * ks][0], a01 = ep0[2 * ks][1];
            const uint32_t a02 = ep0[2 * ks + 1][0], a03 = ep0[2 * ks + 1][1];
            const uint32_t a10 = ep1[2 * ks][0], a11 = ep1[2 * ks][1];
            const uint32_t a12 = ep1[2 * ks + 1][0], a13 = ep1[2 * ks + 1][1];
            mma_f16(oA0, a00, a01, a02, a03, v0, v1);
            mma_f16(oB0, a00, a01, a02, a03, w0, w1);
            mma_f16(oA1, a10, a11, a12, a13, v0, v1);
            mma_f16(oB1, a10, a11, a12, a13, w0, w1);
        }

        // ---- normalize + store O (single fp16) as out-proj B fragments ----
        {
            const float r0 = 1.f / s00;
            const float r1 = 1.f / s01;
            ofp[cA0]       = make_uint2(packh(oA0[0] * r0, oA0[1] * r0),
                                        packh(oB0[0] * r0, oB0[1] * r0));
            ofp[cA0 + 256] = make_uint2(packh(oA0[2] * r1, oA0[3] * r1),
                                        packh(oB0[2] * r1, oB0[3] * r1));
        }
        {
            const float r0 = 1.f / s10;
            const float r1 = 1.f / s11;
            ofp[cA1]       = make_uint2(packh(oA1[0] * r0, oA1[1] * r0),
                                        packh(oB1[0] * r0, oB1[1] * r0));
            ofp[cA1 + 256] = make_uint2(packh(oA1[2] * r1, oA1[3] * r1),
                                        packh(oB1[2] * r1, oB1[3] * r1));
        }
    }
    __syncthreads();

    // ---------- out = Wout @ O + bout : 16 tasks; 8 warps x 2 iters ----------
    #pragma unroll 1
    for (int ti = 0; ti < 2; ++ti) {
        const int gw    = wid + ti * 8;
        const int ch    = 6 + (gw >> 3);
        const int wrb   = (gw >> 1) & 3;
        const int nhalf = gw & 1;
        const uint4* ph = gWh + ((ch * 4 + wrb) * 8) * 32 + lane;
        const uint4* pl = gWl + ((ch * 4 + wrb) * 8) * 32 + lane;
        float d[4][4];
        #pragma unroll
        for (int nt = 0; nt < 4; ++nt)
            #pragma unroll
            for (int j = 0; j < 4; ++j) d[nt][j] = 0.f;
        #pragma unroll 2
        for (int ks = 0; ks < 8; ++ks) {
            const uint4 ah = __ldg(ph + ks * 32);
            const uint4 al = __ldg(pl + ks * 32);
            #pragma unroll
            for (int nt = 0; nt < 4; ++nt) {
                const uint2 bb = ofp[((nhalf * 4 + nt) * 8 + ks) * 32 + lane];
                mma_f16(d[nt], ah.x, ah.y, ah.z, ah.w, bb.x, bb.y);
                mma_f16(d[nt], al.x, al.y, al.z, al.w, bb.x, bb.y);
            }
        }
        const int e0 = (ch - 6) * 64 + wrb * 16 + g;
        const float bb0 = __ldg(bout + e0);
        const float bb1 = __ldg(bout + e0 + 8);
        float* o0 = out + (size_t)b * CDIM * SDIM + (size_t)e0 * SDIM + n * 64 + nhalf * 32 + t4 * 2;
        float* o1 = o0 + (size_t)8 * SDIM;
        #pragma unroll
        for (int nt = 0; nt < 4; ++nt) {
            *reinterpret_cast<float2*>(o0 + nt * 8) = make_float2(d[nt][0] + bb0, d[nt][1] + bb0);
            *reinterpret_cast<float2*>(o1 + nt * 8) = make_float2(d[nt][2] + bb1, d[nt][3] + bb1);
        }
    }
}

extern "C" void kernel_launch(void* const* d_in, const int* in_sizes, int n_in,
                              void* d_out, int out_size)
{
    (void)in_sizes; (void)n_in; (void)out_size;
    const float* x    = (const float*)d_in[0];
    const float* Wqkv = (const float*)d_in[1];
    const float* Wout = (const float*)d_in[2];
    const float* bout = (const float*)d_in[3];
    float* out = (float*)d_out;

    prep_weights<<<32, 256>>>(Wqkv, Wout);

    cudaFuncSetAttribute(lwa3d_mma, cudaFuncAttributeMaxDynamicSharedMemorySize, SMEM_BYTES);
    dim3 grid(NWIN, 2);
    lwa3d_mma<<<grid, 256, SMEM_BYTES>>>(x, bout, out);
}

// round 15
// speedup vs baseline: 1.1475x; 1.1475x over previous
#include <cuda_runtime.h>
#include <cuda_bf16.h>
#include <cuda_fp16.h>
#include <cstdint>

// LocalWindowAttention3D R15: R13 base + QKV in fp16 (W 2-term x x single)
// -> 2 MMAs/step in QKV (was 3), halved QKV B-frag LDS.
// QK bf16 3-term, PV fp16 (P single, V 2-term), out-proj fp16 2-term.
// 512 thr/CTA, 1 CTA/SM, 4 syncs.

namespace {
constexpr int CDIM = 128;
constexpr int SDIM = 110592;      // 48^3
constexpr int NWIN = 1728;        // 12^3
constexpr int XP   = 72;          // xs gather pitch (floats)
// ---- smem plan (bytes) ----
constexpr int O_QFH = 0;          // 2048 uint2 = 16384
constexpr int O_QFL = 16384;
constexpr int O_KFH = 32768;
constexpr int O_KFL = 49152;      // -> 65536
constexpr int O_VF  = 65536;      // uint2[16*264] = 33792 -> 99328
constexpr int O_OF  = 99328;      // uint2[2048] = 16384 -> 115712
// aliases (time-disjoint):
constexpr int O_XS  = 65536;      // gather scratch 36864 (dead before vf writes)
constexpr int O_XB  = 102400;     // x frags uint2[2048] = 16384 (dead before of reads)
constexpr int SMEM_BYTES = 135168;
constexpr int VST = 264;          // vf cblk stride in uint2 cells
}

// Weight fragment images (ALL fp16 hi/lo): [ch(8)][wrb(4)][ks(8)][lane(32)] uint4.
// ch 0..5 = Wqkv, k-map pairs (c0+t4, c0+t4+4), (c0+8+t4, c0+12+t4).
// ch 6..7 = Wout, k-map pairs (c0+2t4, +1), (c0+2t4+8, +9).
__device__ uint4 gWh[8 * 4 * 8 * 32];
__device__ uint4 gWl[8 * 4 * 8 * 32];

__device__ __forceinline__ void split2(float a, float b, uint32_t& hi, uint32_t& lo) {
    __nv_bfloat162 h = __floats2bfloat162_rn(a, b);
    const float ra = a - __low2float(h);
    const float rb = b - __high2float(h);
    __nv_bfloat162 l = __floats2bfloat162_rn(ra, rb);
    hi = *reinterpret_cast<uint32_t*>(&h);
    lo = *reinterpret_cast<uint32_t*>(&l);
}
__device__ __forceinline__ void split2h(float a, float b, uint32_t& hi, uint32_t& lo) {
    __half2 h = __floats2half2_rn(a, b);
    const float ra = a - __half2float(__low2half(h));
    const float rb = b - __half2float(__high2half(h));
    __half2 l = __floats2half2_rn(ra, rb);
    hi = *reinterpret_cast<uint32_t*>(&h);
    lo = *reinterpret_cast<uint32_t*>(&l);
}
__device__ __forceinline__ uint32_t packh(float a, float b) {
    __half2 h = __floats2half2_rn(a, b);
    return *reinterpret_cast<uint32_t*>(&h);
}
__device__ __forceinline__ float ex2(float x) {
    float r;
    asm("ex2.approx.f32 %0, %1;" : "=f"(r) : "f"(x));
    return r;
}
__device__ __forceinline__ void mma_bf16(float* d, uint32_t a0, uint32_t a1, uint32_t a2,
                                         uint32_t a3, uint32_t b0, uint32_t b1) {
    asm volatile(
        "mma.sync.aligned.m16n8k16.row.col.f32.bf16.bf16.f32 "
        "{%0,%1,%2,%3}, {%4,%5,%6,%7}, {%8,%9}, {%0,%1,%2,%3};"
        : "+f"(d[0]), "+f"(d[1]), "+f"(d[2]), "+f"(d[3])
        : "r"(a0), "r"(a1), "r"(a2), "r"(a3), "r"(b0), "r"(b1));
}
__device__ __forceinline__ void mma_f16(float* d, uint32_t a0, uint32_t a1, uint32_t a2,
                                        uint32_t a3, uint32_t b0, uint32_t b1) {
    asm volatile(
        "mma.sync.aligned.m16n8k16.row.col.f32.f16.f16.f32 "
        "{%0,%1,%2,%3}, {%4,%5,%6,%7}, {%8,%9}, {%0,%1,%2,%3};"
        : "+f"(d[0]), "+f"(d[1]), "+f"(d[2]), "+f"(d[3])
        : "r"(a0), "r"(a1), "r"(a2), "r"(a3), "r"(b0), "r"(b1));
}

__global__ void prep_weights(const float* __restrict__ Wqkv, const float* __restrict__ Wout) {
    const int idx = blockIdx.x * 256 + threadIdx.x;     // 8192 frags
    if (idx >= 8192) return;
    const int lane = idx & 31;
    const int ks   = (idx >> 5) & 7;
    const int wrb  = (idx >> 8) & 3;
    const int ch   = idx >> 10;
    const int g = lane >> 2, t4 = lane & 3;
    const int e0 = ch * 64 + wrb * 16 + g;
    const float* W0 = (ch < 6) ? (Wqkv + (size_t)e0 * CDIM) : (Wout + (size_t)(e0 - 384) * CDIM);
    const float* W8 = W0 + 8 * CDIM;
    const int c0 = ks * 16;
    int cs0, cs1, cs2, cs3;
    if (ch < 6) { cs0 = c0 + t4;     cs1 = c0 + t4 + 4;     cs2 = c0 + 8 + t4;      cs3 = c0 + 12 + t4; }
    else        { cs0 = c0 + t4 * 2; cs1 = cs0 + 1;         cs2 = cs0 + 8;          cs3 = cs0 + 9; }
    uint4 h, l;
    split2h(W0[cs0], W0[cs1], h.x, l.x);
    split2h(W8[cs0], W8[cs1], h.y, l.y);
    split2h(W0[cs2], W0[cs3], h.z, l.z);
    split2h(W8[cs2], W8[cs3], h.w, l.w);
    gWh[idx] = h;
    gWl[idx] = l;
}

__global__ __launch_bounds__(512, 1)
void lwa3d_mma(const float* __restrict__ x, const float* __restrict__ bout,
               float* __restrict__ out)
{
    extern __shared__ char smc[];
    uint2* qfh = reinterpret_cast<uint2*>(smc + O_QFH);
    uint2* qfl = reinterpret_cast<uint2*>(smc + O_QFL);
    uint2* kfh = reinterpret_cast<uint2*>(smc + O_KFH);
    uint2* kfl = reinterpret_cast<uint2*>(smc + O_KFL);
    uint32_t* qfhw = reinterpret_cast<uint32_t*>(smc + O_QFH);
    uint32_t* qflw = reinterpret_cast<uint32_t*>(smc + O_QFL);
    uint32_t* kfhw = reinterpret_cast<uint32_t*>(smc + O_KFH);
    uint32_t* kflw = reinterpret_cast<uint32_t*>(smc + O_KFL);
    uint2* vfp = reinterpret_cast<uint2*>(smc + O_VF);
    uint2* ofp = reinterpret_cast<uint2*>(smc + O_OF);
    float* xs  = reinterpret_cast<float*>(smc + O_XS);
    uint2* xbp = reinterpret_cast<uint2*>(smc + O_XB);

    const int tid  = threadIdx.x;
    const int wid  = tid >> 5;
    const int lane = tid & 31;
    const int g    = lane >> 2;
    const int t4   = lane & 3;
    const int n = blockIdx.x;
    const int b = blockIdx.y;
    // 128^-0.5 * log2(e): Q pre-scale so softmax uses ex2 directly
    const float scale = 0.12751741578f;

    // ---------- gather x window into xs [128c][64t] ----------
    {
        const int ndi = n / 144, nhi = (n / 12) % 12, nwi = n % 12;
        const float* xb = x + (size_t)b * CDIM * SDIM;
        const int sbase = ((ndi * 4) * 48 + nhi * 4) * 48 + nwi * 4;
        for (int i = tid; i < CDIM * 16; i += 512) {
            const int c = i >> 4;
            const int gg = i & 15;
            const int s0 = sbase + ((gg >> 2) * 48 + (gg & 3)) * 48;
            *reinterpret_cast<float4*>(xs + c * XP + gg * 4) =
                *reinterpret_cast<const float4*>(xb + (size_t)c * SDIM + s0);
        }
    }
    __syncthreads();

    // ---------- build single-term fp16 x B-fragments ----------
    for (int cell = tid; cell < 2048; cell += 512) {
        const int l2 = cell & 31;
        const int ks = (cell >> 5) & 7;
        const int tb = cell >> 8;
        const int t  = tb * 8 + (l2 >> 2);
        const int c0 = ks * 16 + (l2 & 3);
        xbp[cell] = make_uint2(packh(xs[c0 * XP + t], xs[(c0 + 4) * XP + t]),
                               packh(xs[(c0 + 8) * XP + t], xs[(c0 + 12) * XP + t]));
    }
    __syncthreads();

    // ---------- QKV = Wqkv @ x : fp16 W2 x x1, 3 chunks/warp sharing B ----------
    {
        const int nhalf = wid & 1;
        const int p0 = (wid >> 1) * 3;          // 3 (ch,wrb) pairs per warp
        const uint4* ph[3];
        const uint4* pl[3];
        #pragma unroll
        for (int i = 0; i < 3; ++i) {
            const int p = p0 + i;
            ph[i] = gWh + (p * 8) * 32 + lane;   // p == ch*4+wrb
            pl[i] = gWl + (p * 8) * 32 + lane;
        }
        float d[3][4][4];
        #pragma unroll
        for (int i = 0; i < 3; ++i)
            #pragma unroll
            for (int nt = 0; nt < 4; ++nt)
                #pragma unroll
                for (int j = 0; j < 4; ++j) d[i][nt][j] = 0.f;

        #pragma unroll
        for (int ks = 0; ks < 8; ++ks) {
            uint2 bb[4];
            #pragma unroll
            for (int nt = 0; nt < 4; ++nt)
                bb[nt] = xbp[((nhalf * 4 + nt) * 8 + ks) * 32 + lane];
            #pragma unroll
            for (int i = 0; i < 3; ++i) {
                const uint4 ah = __ldg(ph[i] + ks * 32);
                const uint4 al = __ldg(pl[i] + ks * 32);
                #pragma unroll
                for (int nt = 0; nt < 4; ++nt) {
                    mma_f16(d[i][nt], ah.x, ah.y, ah.z, ah.w, bb[nt].x, bb[nt].y);
                    mma_f16(d[i][nt], al.x, al.y, al.z, al.w, bb[nt].x, bb[nt].y);
                }
            }
        }

        // epilogues (identical maps to R13)
        #pragma unroll
        for (int i = 0; i < 3; ++i) {
            const int p = p0 + i;
            const int ch  = p >> 2;
            const int wrb = p & 3;
            if (ch < 4) {
                const int h = (ch & 1) * 4 + wrb;
                uint32_t* fh = (ch < 2) ? qfhw : kfhw;
                uint32_t* fl = (ch < 2) ? qflw : kflw;
                const float sc = (ch < 2) ? scale : 1.f;
                #pragma unroll
                for (int nt = 0; nt < 4; ++nt) {
                    const int tb = nhalf * 4 + nt;
                    uint32_t hh0, ll0, hh1, ll1;
                    split2(d[i][nt][0] * sc, d[i][nt][2] * sc, hh0, ll0);
                    split2(d[i][nt][1] * sc, d[i][nt][3] * sc, hh1, ll1);
                    const int base = (tb * 8 + h) * 32 + (g & 3);
                    const int i0 = ((base + (2 * t4) * 4) << 1) | (g >> 2);
                    const int i1 = ((base + (2 * t4 + 1) * 4) << 1) | (g >> 2);
                    fh[i0] = hh0; fl[i0] = ll0;
                    fh[i1] = hh1; fl[i1] = ll1;
                }
            } else {
                const int cb0 = (ch & 1) * 8 + wrb * 2;
                const int lane2 = g * 4 + t4;
                #pragma unroll
                for (int nt = 0; nt < 4; ++nt) {
                    const int kb = nhalf * 4 + nt;
                    uint32_t h0, l0, h1, l1;
                    split2h(d[i][nt][0], d[i][nt][1], h0, l0);
                    split2h(d[i][nt][2], d[i][nt][3], h1, l1);
                    vfp[cb0 * VST + kb * 32 + lane2] = make_uint2(h0, l0);
                    vfp[(cb0 + 1) * VST + kb * 32 + lane2] = make_uint2(h1, l1);
                }
            }
        }
    }
    __syncthreads();

    // ---------- attention: warp owns head h = wid>>1, q-blocks mb0, mb0+1 ----------
    {
        const int h   = wid >> 1;
        const int mb0 = (wid & 1) * 2;

        const int cA0 = (2 * mb0 * 8 + h) * 32 + lane;
        const int cA1 = (2 * (mb0 + 1) * 8 + h) * 32 + lane;
        const uint2 A0h0 = qfh[cA0], A0h1 = qfh[cA0 + 256];
        const uint2 A0l0 = qfl[cA0], A0l1 = qfl[cA0 + 256];
        const uint2 A1h0 = qfh[cA1], A1h1 = qfh[cA1 + 256];
        const uint2 A1l0 = qfl[cA1], A1l1 = qfl[cA1 + 256];

        uint32_t ep0[8][2], ep1[8][2];
        float s00 = 0.f, s01 = 0.f, s10 = 0.f, s11 = 0.f;
        #pragma unroll 2
        for (int kb = 0; kb < 8; ++kb) {
            const int cB = (kb * 8 + h) * 32 + lane;
            const uint2 Bh = kfh[cB];
            const uint2 Bl = kfl[cB];
            float d0[4] = {0.f, 0.f, 0.f, 0.f};
            float d1[4] = {0.f, 0.f, 0.f, 0.f};
            mma_bf16(d0, A0h0.x, A0h1.x, A0h0.y, A0h1.y, Bh.x, Bh.y);
            mma_bf16(d0, A0h0.x, A0h1.x, A0h0.y, A0h1.y, Bl.x, Bl.y);
            mma_bf16(d0, A0l0.x, A0l1.x, A0l0.y, A0l1.y, Bh.x, Bh.y);
            mma_bf16(d1, A1h0.x, A1h1.x, A1h0.y, A1h1.y, Bh.x, Bh.y);
            mma_bf16(d1, A1h0.x, A1h1.x, A1h0.y, A1h1.y, Bl.x, Bl.y);
            mma_bf16(d1, A1l0.x, A1l1.x, A1l0.y, A1l1.y, Bh.x, Bh.y);
            const float e00 = ex2(d0[0]);
            const float e01 = ex2(d0[1]);
            const float e02 = ex2(d0[2]);
            const float e03 = ex2(d0[3]);
            s00 += e00 + e01;
            s01 += e02 + e03;
            ep0[kb][0] = packh(e00, e01);
            ep0[kb][1] = packh(e02, e03);
            const float e10 = ex2(d1[0]);
            const float e11 = ex2(d1[1]);
            const float e12 = ex2(d1[2]);
            const float e13 = ex2(d1[3]);
            s10 += e10 + e11;
            s11 += e12 + e13;
            ep1[kb][0] = packh(e10, e11);
            ep1[kb][1] = packh(e12, e13);
        }
        s00 += __shfl_xor_sync(0xFFFFFFFF, s00, 1);
        s00 += __shfl_xor_sync(0xFFFFFFFF, s00, 2);
        s01 += __shfl_xor_sync(0xFFFFFFFF, s01, 1);
        s01 += __shfl_xor_sync(0xFFFFFFFF, s01, 2);
        s10 += __shfl_xor_sync(0xFFFFFFFF, s10, 1);
        s10 += __shfl_xor_sync(0xFFFFFFFF, s10, 2);
        s11 += __shfl_xor_sync(0xFFFFFFFF, s11, 1);
        s11 += __shfl_xor_sync(0xFFFFFFFF, s11, 2);

        // ---- PV (fp16, P single x V 2-term): V frags shared by both q-blocks ----
        float oA0[4] = {0.f, 0.f, 0.f, 0.f};
        float oB0[4] = {0.f, 0.f, 0.f, 0.f};
        float oA1[4] = {0.f, 0.f, 0.f, 0.f};
        float oB1[4] = {0.f, 0.f, 0.f, 0.f};
        #pragma unroll
        for (int ks = 0; ks < 4; ++ks) {
            const int ib = (2 * h) * VST + (2 * ks) * 32 + lane;
            const uint2 c00 = vfp[ib],       c01 = vfp[ib + 32];
            const uint2 c10 = vfp[ib + VST], c11 = vfp[ib + VST + 32];
            const uint32_t a00 = ep0[2 * ks][0], a01 = ep0[2 * ks][1];
            const uint32_t a02 = ep0[2 * ks + 1][0], a03 = ep0[2 * ks + 1][1];
            const uint32_t a10 = ep1[2 * ks][0], a11 = ep1[2 * ks][1];
            const uint32_t a12 = ep1[2 * ks + 1][0], a13 = ep1[2 * ks + 1][1];
            mma_f16(oA0, a00, a01, a02, a03, c00.x, c01.x);
            mma_f16(oA0, a00, a01, a02, a03, c00.y, c01.y);
            mma_f16(oB0, a00, a01, a02, a03, c10.x, c11.x);
            mma_f16(oB0, a00, a01, a02, a03, c10.y, c11.y);
            mma_f16(oA1, a10, a11, a12, a13, c00.x, c01.x);
            mma_f16(oA1, a10, a11, a12, a13, c00.y, c01.y);
            mma_f16(oB1, a10, a11, a12, a13, c10.x, c11.x);
            mma_f16(oB1, a10, a11, a12, a13, c10.y, c11.y);
        }

        // ---- normalize + store O (single fp16) as out-proj B fragments ----
        {
            const float r0 = 1.f / s00;
            const float r1 = 1.f / s01;
            ofp[cA0]       = make_uint2(packh(oA0[0] * r0, oA0[1] * r0),
                                        packh(oB0[0] * r0, oB0[1] * r0));
            ofp[cA0 + 256] = make_uint2(packh(oA0[2] * r1, oA0[3] * r1),
                                        packh(oB0[2] * r1, oB0[3] * r1));
        }
        {
            const float r0 = 1.f / s10;
            const float r1 = 1.f / s11;
            ofp[cA1]       = make_uint2(packh(oA1[0] * r0, oA1[1] * r0),
                                        packh(oB1[0] * r0, oB1[1] * r0));
            ofp[cA1 + 256] = make_uint2(packh(oA1[2] * r1, oA1[3] * r1),
                                        packh(oB1[2] * r1, oB1[3] * r1));
        }
    }
    __syncthreads();

    // ---------- out = Wout @ O + bout : fp16 2-term, 16 warp-tasks ----------
    {
        const int ch    = 6 + (wid >> 3);
        const int wrb   = (wid >> 1) & 3;
        const int nhalf = wid & 1;
        const uint4* ph = gWh + ((ch * 4 + wrb) * 8) * 32 + lane;
        const uint4* pl = gWl + ((ch * 4 + wrb) * 8) * 32 + lane;
        float d[4][4];
        #pragma unroll
        for (int nt = 0; nt < 4; ++nt)
            #pragma unroll
            for (int j = 0; j < 4; ++j) d[nt][j] = 0.f;
        #pragma unroll 2
        for (int ks = 0; ks < 8; ++ks) {
            const uint4 ah = __ldg(ph + ks * 32);
            const uint4 al = __ldg(pl + ks * 32);
            #pragma unroll
            for (int nt = 0; nt < 4; ++nt) {
                const uint2 bb = ofp[((nhalf * 4 + nt) * 8 + ks) * 32 + lane];
                mma_f16(d[nt], ah.x, ah.y, ah.z, ah.w, bb.x, bb.y);
                mma_f16(d[nt], al.x, al.y, al.z, al.w, bb.x, bb.y);
            }
        }
        const int e0 = (ch - 6) * 64 + wrb * 16 + g;
        const float bb0 = __ldg(bout + e0);
        const float bb1 = __ldg(bout + e0 + 8);
        float* o0 = out + (size_t)b * CDIM * SDIM + (size_t)e0 * SDIM + n * 64 + nhalf * 32 + t4 * 2;
        float* o1 = o0 + (size_t)8 * SDIM;
        #pragma unroll
        for (int nt = 0; nt < 4; ++nt) {
            *reinterpret_cast<float2*>(o0 + nt * 8) = make_float2(d[nt][0] + bb0, d[nt][1] + bb0);
            *reinterpret_cast<float2*>(o1 + nt * 8) = make_float2(d[nt][2] + bb1, d[nt][3] + bb1);
        }
    }
}

extern "C" void kernel_launch(void* const* d_in, const int* in_sizes, int n_in,
                              void* d_out, int out_size)
{
    (void)in_sizes; (void)n_in; (void)out_size;
    const float* x    = (const float*)d_in[0];
    const float* Wqkv = (const float*)d_in[1];
    const float* Wout = (const float*)d_in[2];
    const float* bout = (const float*)d_in[3];
    float* out = (float*)d_out;

    prep_weights<<<32, 256>>>(Wqkv, Wout);

    cudaFuncSetAttribute(lwa3d_mma, cudaFuncAttributeMaxDynamicSharedMemorySize, SMEM_BYTES);
    dim3 grid(NWIN, 2);
    lwa3d_mma<<<grid, 512, SMEM_BYTES>>>(x, bout, out);
}

// round 17
// speedup vs baseline: 1.2546x; 1.0934x over previous
#include <cuda_runtime.h>
#include <cuda_bf16.h>
#include <cuda_fp16.h>
#include <cstdint>

// LocalWindowAttention3D R16: fp16 everywhere.
// QKV: W 2-term x x single (2 MMA/step). QK: Q 2-term x K single (2).
// PV: P single x V single (1). Out-proj: W single x O single (1).
// 4352 MMAs/CTA. 512 thr/CTA, 1 CTA/SM, 96KB smem, 4 syncs.

namespace {
constexpr int CDIM = 128;
constexpr int SDIM = 110592;      // 48^3
constexpr int NWIN = 1728;        // 12^3
constexpr int XP   = 72;          // xs gather pitch (floats)
// ---- smem plan (bytes), total 98304 ----
constexpr int O_QFH = 0;          // u32[4096] = 16384 (Q hi, fp16x2 pairs)
constexpr int O_QFL = 16384;      // Q lo
constexpr int O_KF  = 32768;      // K single, 16384
constexpr int O_VF  = 49152;      // V single, u32[16*256] = 16384 -> 65536
constexpr int O_OF  = 65536;      // O frags uint2[2048] = 16384 -> 81920
constexpr int O_XS  = 32768;      // gather scratch 36864 (dead before kf/vf/of writes)
constexpr int O_XB  = 81920;      // x frags uint2[2048] = 16384 -> 98304
constexpr int SMEM_BYTES = 98304;
constexpr int VST = 256;          // vf cblk stride in u32 (stride-1 access, no conflicts)
}

// Weight fragment images (fp16): [ch(8)][wrb(4)][ks(8)][lane(32)] uint4.
// ch 0..5 = Wqkv hi/lo 2-term, k-map pairs (c0+t4, +4), (c0+8+t4, +12).
// ch 6..7 = Wout single (gWh only), k-map pairs (c0+2t4, +1), (c0+2t4+8, +9).
__device__ uint4 gWh[8 * 4 * 8 * 32];
__device__ uint4 gWl[8 * 4 * 8 * 32];

__device__ __forceinline__ void split2h(float a, float b, uint32_t& hi, uint32_t& lo) {
    __half2 h = __floats2half2_rn(a, b);
    const float ra = a - __half2float(__low2half(h));
    const float rb = b - __half2float(__high2half(h));
    __half2 l = __floats2half2_rn(ra, rb);
    hi = *reinterpret_cast<uint32_t*>(&h);
    lo = *reinterpret_cast<uint32_t*>(&l);
}
__device__ __forceinline__ uint32_t packh(float a, float b) {
    __half2 h = __floats2half2_rn(a, b);
    return *reinterpret_cast<uint32_t*>(&h);
}
__device__ __forceinline__ float ex2(float x) {
    float r;
    asm("ex2.approx.f32 %0, %1;" : "=f"(r) : "f"(x));
    return r;
}
__device__ __forceinline__ void mma_f16(float* d, uint32_t a0, uint32_t a1, uint32_t a2,
                                        uint32_t a3, uint32_t b0, uint32_t b1) {
    asm volatile(
        "mma.sync.aligned.m16n8k16.row.col.f32.f16.f16.f32 "
        "{%0,%1,%2,%3}, {%4,%5,%6,%7}, {%8,%9}, {%0,%1,%2,%3};"
        : "+f"(d[0]), "+f"(d[1]), "+f"(d[2]), "+f"(d[3])
        : "r"(a0), "r"(a1), "r"(a2), "r"(a3), "r"(b0), "r"(b1));
}

__global__ void prep_weights(const float* __restrict__ Wqkv, const float* __restrict__ Wout) {
    const int idx = blockIdx.x * 256 + threadIdx.x;     // 8192 frags
    if (idx >= 8192) return;
    const int lane = idx & 31;
    const int ks   = (idx >> 5) & 7;
    const int wrb  = (idx >> 8) & 3;
    const int ch   = idx >> 10;
    const int g = lane >> 2, t4 = lane & 3;
    const int e0 = ch * 64 + wrb * 16 + g;
    const float* W0 = (ch < 6) ? (Wqkv + (size_t)e0 * CDIM) : (Wout + (size_t)(e0 - 384) * CDIM);
    const float* W8 = W0 + 8 * CDIM;
    const int c0 = ks * 16;
    if (ch < 6) {
        const int cs0 = c0 + t4, cs1 = c0 + t4 + 4, cs2 = c0 + 8 + t4, cs3 = c0 + 12 + t4;
        uint4 h, l;
        split2h(W0[cs0], W0[cs1], h.x, l.x);
        split2h(W8[cs0], W8[cs1], h.y, l.y);
        split2h(W0[cs2], W0[cs3], h.z, l.z);
        split2h(W8[cs2], W8[cs3], h.w, l.w);
        gWh[idx] = h;
        gWl[idx] = l;
    } else {
        const int cs0 = c0 + t4 * 2, cs1 = cs0 + 1, cs2 = cs0 + 8, cs3 = cs0 + 9;
        uint4 h;
        h.x = packh(W0[cs0], W0[cs1]);
        h.y = packh(W8[cs0], W8[cs1]);
        h.z = packh(W0[cs2], W0[cs3]);
        h.w = packh(W8[cs2], W8[cs3]);
        gWh[idx] = h;
    }
}

__global__ __launch_bounds__(512, 1)
void lwa3d_mma(const float* __restrict__ x, const float* __restrict__ bout,
               float* __restrict__ out)
{
    extern __shared__ char smc[];
    uint2* qfh = reinterpret_cast<uint2*>(smc + O_QFH);
    uint2* qfl = reinterpret_cast<uint2*>(smc + O_QFL);
    uint2* kf2 = reinterpret_cast<uint2*>(smc + O_KF);
    uint32_t* qfhw = reinterpret_cast<uint32_t*>(smc + O_QFH);
    uint32_t* qflw = reinterpret_cast<uint32_t*>(smc + O_QFL);
    uint32_t* kfw  = reinterpret_cast<uint32_t*>(smc + O_KF);
    uint32_t* vf = reinterpret_cast<uint32_t*>(smc + O_VF);
    uint2* ofp = reinterpret_cast<uint2*>(smc + O_OF);
    float* xs  = reinterpret_cast<float*>(smc + O_XS);
    uint2* xbp = reinterpret_cast<uint2*>(smc + O_XB);

    const int tid  = threadIdx.x;
    const int wid  = tid >> 5;
    const int lane = tid & 31;
    const int g    = lane >> 2;
    const int t4   = lane & 3;
    const int n = blockIdx.x;
    const int b = blockIdx.y;
    // 128^-0.5 * log2(e): Q pre-scale so softmax uses ex2 directly
    const float scale = 0.12751741578f;

    // ---------- gather x window into xs [128c][64t] ----------
    {
        const int ndi = n / 144, nhi = (n / 12) % 12, nwi = n % 12;
        const float* xb = x + (size_t)b * CDIM * SDIM;
        const int sbase = ((ndi * 4) * 48 + nhi * 4) * 48 + nwi * 4;
        for (int i = tid; i < CDIM * 16; i += 512) {
            const int c = i >> 4;
            const int gg = i & 15;
            const int s0 = sbase + ((gg >> 2) * 48 + (gg & 3)) * 48;
            *reinterpret_cast<float4*>(xs + c * XP + gg * 4) =
                *reinterpret_cast<const float4*>(xb + (size_t)c * SDIM + s0);
        }
    }
    __syncthreads();

    // ---------- build single-term fp16 x B-fragments ----------
    for (int cell = tid; cell < 2048; cell += 512) {
        const int l2 = cell & 31;
        const int ks = (cell >> 5) & 7;
        const int tb = cell >> 8;
        const int t  = tb * 8 + (l2 >> 2);
        const int c0 = ks * 16 + (l2 & 3);
        xbp[cell] = make_uint2(packh(xs[c0 * XP + t], xs[(c0 + 4) * XP + t]),
                               packh(xs[(c0 + 8) * XP + t], xs[(c0 + 12) * XP + t]));
    }
    __syncthreads();

    // ---------- QKV = Wqkv @ x : fp16 W2 x x1, 3 chunks/warp sharing B ----------
    {
        const int nhalf = wid & 1;
        const int p0 = (wid >> 1) * 3;          // 3 (ch,wrb) pairs per warp
        const uint4* ph[3];
        const uint4* pl[3];
        #pragma unroll
        for (int i = 0; i < 3; ++i) {
            const int p = p0 + i;
            ph[i] = gWh + (p * 8) * 32 + lane;   // p == ch*4+wrb
            pl[i] = gWl + (p * 8) * 32 + lane;
        }
        float d[3][4][4];
        #pragma unroll
        for (int i = 0; i < 3; ++i)
            #pragma unroll
            for (int nt = 0; nt < 4; ++nt)
                #pragma unroll
                for (int j = 0; j < 4; ++j) d[i][nt][j] = 0.f;

        #pragma unroll
        for (int ks = 0; ks < 8; ++ks) {
            uint2 bb[4];
            #pragma unroll
            for (int nt = 0; nt < 4; ++nt)
                bb[nt] = xbp[((nhalf * 4 + nt) * 8 + ks) * 32 + lane];
            #pragma unroll
            for (int i = 0; i < 3; ++i) {
                const uint4 ah = __ldg(ph[i] + ks * 32);
                const uint4 al = __ldg(pl[i] + ks * 32);
                #pragma unroll
                for (int nt = 0; nt < 4; ++nt) {
                    mma_f16(d[i][nt], ah.x, ah.y, ah.z, ah.w, bb[nt].x, bb[nt].y);
                    mma_f16(d[i][nt], al.x, al.y, al.z, al.w, bb[nt].x, bb[nt].y);
                }
            }
        }

        // epilogues: Q -> fp16 hi/lo frags; K -> fp16 single; V -> fp16 single
        #pragma unroll
        for (int i = 0; i < 3; ++i) {
            const int p = p0 + i;
            const int ch  = p >> 2;
            const int wrb = p & 3;
            if (ch < 2) {          // Q: 2-term fp16, pre-scaled
                const int h = (ch & 1) * 4 + wrb;
                #pragma unroll
                for (int nt = 0; nt < 4; ++nt) {
                    const int tb = nhalf * 4 + nt;
                    uint32_t hh0, ll0, hh1, ll1;
                    split2h(d[i][nt][0] * scale, d[i][nt][2] * scale, hh0, ll0);
                    split2h(d[i][nt][1] * scale, d[i][nt][3] * scale, hh1, ll1);
                    const int base = (tb * 8 + h) * 32 + (g & 3);
                    const int i0 = ((base + (2 * t4) * 4) << 1) | (g >> 2);
                    const int i1 = ((base + (2 * t4 + 1) * 4) << 1) | (g >> 2);
                    qfhw[i0] = hh0; qflw[i0] = ll0;
                    qfhw[i1] = hh1; qflw[i1] = ll1;
                }
            } else if (ch < 4) {   // K: single fp16
                const int h = (ch & 1) * 4 + wrb;
                #pragma unroll
                for (int nt = 0; nt < 4; ++nt) {
                    const int tb = nhalf * 4 + nt;
                    const int base = (tb * 8 + h) * 32 + (g & 3);
                    const int i0 = ((base + (2 * t4) * 4) << 1) | (g >> 2);
                    const int i1 = ((base + (2 * t4 + 1) * 4) << 1) | (g >> 2);
                    kfw[i0] = packh(d[i][nt][0], d[i][nt][2]);
                    kfw[i1] = packh(d[i][nt][1], d[i][nt][3]);
                }
            } else {               // V: single fp16
                const int cb0 = (ch & 1) * 8 + wrb * 2;
                #pragma unroll
                for (int nt = 0; nt < 4; ++nt) {
                    const int kb = nhalf * 4 + nt;
                    vf[cb0 * VST + kb * 32 + lane]       = packh(d[i][nt][0], d[i][nt][1]);
                    vf[(cb0 + 1) * VST + kb * 32 + lane] = packh(d[i][nt][2], d[i][nt][3]);
                }
            }
        }
    }
    __syncthreads();

    // ---------- attention: warp owns head h = wid>>1, q-blocks mb0, mb0+1 ----------
    {
        const int h   = wid >> 1;
        const int mb0 = (wid & 1) * 2;

        const int cA0 = (2 * mb0 * 8 + h) * 32 + lane;
        const int cA1 = (2 * (mb0 + 1) * 8 + h) * 32 + lane;
        const uint2 A0h0 = qfh[cA0], A0h1 = qfh[cA0 + 256];
        const uint2 A0l0 = qfl[cA0], A0l1 = qfl[cA0 + 256];
        const uint2 A1h0 = qfh[cA1], A1h1 = qfh[cA1 + 256];
        const uint2 A1l0 = qfl[cA1], A1l1 = qfl[cA1 + 256];

        uint32_t ep0[8][2], ep1[8][2];
        float s00 = 0.f, s01 = 0.f, s10 = 0.f, s11 = 0.f;
        #pragma unroll 2
        for (int kb = 0; kb < 8; ++kb) {
            const uint2 Bh = kf2[(kb * 8 + h) * 32 + lane];
            float d0[4] = {0.f, 0.f, 0.f, 0.f};
            float d1[4] = {0.f, 0.f, 0.f, 0.f};
            mma_f16(d0, A0h0.x, A0h1.x, A0h0.y, A0h1.y, Bh.x, Bh.y);
            mma_f16(d0, A0l0.x, A0l1.x, A0l0.y, A0l1.y, Bh.x, Bh.y);
            mma_f16(d1, A1h0.x, A1h1.x, A1h0.y, A1h1.y, Bh.x, Bh.y);
            mma_f16(d1, A1l0.x, A1l1.x, A1l0.y, A1l1.y, Bh.x, Bh.y);
            const float e00 = ex2(d0[0]);
            const float e01 = ex2(d0[1]);
            const float e02 = ex2(d0[2]);
            const float e03 = ex2(d0[3]);
            s00 += e00 + e01;
            s01 += e02 + e03;
            ep0[kb][0] = packh(e00, e01);
            ep0[kb][1] = packh(e02, e03);
            const float e10 = ex2(d1[0]);
            const float e11 = ex2(d1[1]);
            const float e12 = ex2(d1[2]);
            const float e13 = ex2(d1[3]);
            s10 += e10 + e11;
            s11 += e12 + e13;
            ep1[kb][0] = packh(e10, e11);
            ep1[kb][1] = packh(e12, e13);
        }
        s00 += __shfl_xor_sync(0xFFFFFFFF, s00, 1);
        s00 += __shfl_xor_sync(0xFFFFFFFF, s00, 2);
        s01 += __shfl_xor_sync(0xFFFFFFFF, s01, 1);
        s01 += __shfl_xor_sync(0xFFFFFFFF, s01, 2);
        s10 += __shfl_xor_sync(0xFFFFFFFF, s10, 1);
        s10 += __shfl_xor_sync(0xFFFFFFFF, s10, 2);
        s11 += __shfl_xor_sync(0xFFFFFFFF, s11, 1);
        s11 += __shfl_xor_sync(0xFFFFFFFF, s11, 2);

        // ---- PV (fp16, P single x V single): V frags shared by both q-blocks ----
        float oA0[4] = {0.f, 0.f, 0.f, 0.f};
        float oB0[4] = {0.f, 0.f, 0.f, 0.f};
        float oA1[4] = {0.f, 0.f, 0.f, 0.f};
        float oB1[4] = {0.f, 0.f, 0.f, 0.f};
        #pragma unroll
        for (int ks = 0; ks < 4; ++ks) {
            const int ib = (2 * h) * VST + (2 * ks) * 32 + lane;
            const uint32_t v0 = vf[ib],       v1 = vf[ib + 32];
            const uint32_t w0 = vf[ib + VST], w1 = vf[ib + VST + 32];
            const uint32_t a00 = ep0[2 * ks][0], a01 = ep0[2 * ks][1];
            const uint32_t a02 = ep0[2 * ks + 1][0], a03 = ep0[2 * ks + 1][1];
            const uint32_t a10 = ep1[2 * ks][0], a11 = ep1[2 * ks][1];
            const uint32_t a12 = ep1[2 * ks + 1][0], a13 = ep1[2 * ks + 1][1];
            mma_f16(oA0, a00, a01, a02, a03, v0, v1);
            mma_f16(oB0, a00, a01, a02, a03, w0, w1);
            mma_f16(oA1, a10, a11, a12, a13, v0, v1);
            mma_f16(oB1, a10, a11, a12, a13, w0, w1);
        }

        // ---- normalize + store O (single fp16) as out-proj B fragments ----
        {
            const float r0 = 1.f / s00;
            const float r1 = 1.f / s01;
            ofp[cA0]       = make_uint2(packh(oA0[0] * r0, oA0[1] * r0),
                                        packh(oB0[0] * r0, oB0[1] * r0));
            ofp[cA0 + 256] = make_uint2(packh(oA0[2] * r1, oA0[3] * r1),
                                        packh(oB0[2] * r1, oB0[3] * r1));
        }
        {
            const float r0 = 1.f / s10;
            const float r1 = 1.f / s11;
            ofp[cA1]       = make_uint2(packh(oA1[0] * r0, oA1[1] * r0),
                                        packh(oB1[0] * r0, oB1[1] * r0));
            ofp[cA1 + 256] = make_uint2(packh(oA1[2] * r1, oA1[3] * r1),
                                        packh(oB1[2] * r1, oB1[3] * r1));
        }
    }
    __syncthreads();

    // ---------- out = Wout @ O + bout : fp16 single x single, 16 warp-tasks ----------
    {
        const int ch    = 6 + (wid >> 3);
        const int wrb   = (wid >> 1) & 3;
        const int nhalf = wid & 1;
        const uint4* ph = gWh + ((ch * 4 + wrb) * 8) * 32 + lane;
        float d[4][4];
        #pragma unroll
        for (int nt = 0; nt < 4; ++nt)
            #pragma unroll
            for (int j = 0; j < 4; ++j) d[nt][j] = 0.f;
        #pragma unroll 2
        for (int ks = 0; ks < 8; ++ks) {
            const uint4 ah = __ldg(ph + ks * 32);
            #pragma unroll
            for (int nt = 0; nt < 4; ++nt) {
                const uint2 bb = ofp[((nhalf * 4 + nt) * 8 + ks) * 32 + lane];
                mma_f16(d[nt], ah.x, ah.y, ah.z, ah.w, bb.x, bb.y);
            }
        }
        const int e0 = (ch - 6) * 64 + wrb * 16 + g;
        const float bb0 = __ldg(bout + e0);
        const float bb1 = __ldg(bout + e0 + 8);
        float* o0 = out + (size_t)b * CDIM * SDIM + (size_t)e0 * SDIM + n * 64 + nhalf * 32 + t4 * 2;
        float* o1 = o0 + (size_t)8 * SDIM;
        #pragma unroll
        for (int nt = 0; nt < 4; ++nt) {
            *reinterpret_cast<float2*>(o0 + nt * 8) = make_float2(d[nt][0] + bb0, d[nt][1] + bb0);
            *reinterpret_cast<float2*>(o1 + nt * 8) = make_float2(d[nt][2] + bb1, d[nt][3] + bb1);
        }
    }
}

extern "C" void kernel_launch(void* const* d_in, const int* in_sizes, int n_in,
                              void* d_out, int out_size)
{
    (void)in_sizes; (void)n_in; (void)out_size;
    const float* x    = (const float*)d_in[0];
    const float* Wqkv = (const float*)d_in[1];
    const float* Wout = (const float*)d_in[2];
    const float* bout = (const float*)d_in[3];
    float* out = (float*)d_out;

    prep_weights<<<32, 256>>>(Wqkv, Wout);

    cudaFuncSetAttribute(lwa3d_mma, cudaFuncAttributeMaxDynamicSharedMemorySize, SMEM_BYTES);
    dim3 grid(NWIN, 2);
    lwa3d_mma<<<grid, 512, SMEM_BYTES>>>(x, bout, out);
}